// round 13
// baseline (speedup 1.0000x reference)
#include <cuda_runtime.h>
#include <cuda_bf16.h>
#include <cstdint>

#define TLEN 128
#define HID  256
#define CTXD 16

#define SBW 280                  // B row stride (bf16 units)
#define SBB 560                  // B row stride (bytes)
#define BROWS 68                 // 64 local t rows + 4 zero rows
#define BSPLH 38080              // one split: 68*560
#define A0_OFF 76160             // A buffer 0 (16 KB)
#define A1_OFF 92544             // A buffer 1 (16 KB)
#define SCR_OFF 108928           // [8][64] floats
#define CF_OFF  110976           // 64 floats
#define ATT_OFF 111232           // 64 floats
#define RED_OFF 111488           // redv[4] + redi[4]
#define SMEM_BYTES 111552
// head overlay (A region, pipeline drained by then)
#define EVW_OFF 76160            // 16x256 f32
#define SWW_OFF 92544            // 256 f32
#define EVS_OFF 93568            // 16x64 f32

#define NSTEP 320                // 64 proj + 8*32 conv steps (16 k-units each)
__device__ __align__(1024) unsigned char gW[(size_t)NSTEP * 16384];

__device__ __forceinline__ void mma_bf16(float* d, uint32_t a0, uint32_t a1, uint32_t a2, uint32_t a3,
                                         uint32_t b0, uint32_t b1) {
    asm("mma.sync.aligned.m16n8k16.row.col.f32.bf16.bf16.f32 "
        "{%0,%1,%2,%3}, {%4,%5,%6,%7}, {%8,%9}, {%0,%1,%2,%3};"
        : "+f"(d[0]), "+f"(d[1]), "+f"(d[2]), "+f"(d[3])
        : "r"(a0), "r"(a1), "r"(a2), "r"(a3), "r"(b0), "r"(b1));
}
__device__ __forceinline__ void split2(float w, __nv_bfloat16& hi, __nv_bfloat16& lo) {
    hi = __float2bfloat16(w);
    lo = __float2bfloat16(w - __bfloat162float(hi));
}
__device__ __forceinline__ unsigned short spc(float w, int sp) {
    __nv_bfloat16 hi = __float2bfloat16(w);
    if (sp == 0) return __bfloat16_as_ushort(hi);
    return __bfloat16_as_ushort(__float2bfloat16(w - __bfloat162float(hi)));
}
__device__ __forceinline__ int PERMC(int k) {
    int v = k & 15, p = v >> 1, bb = v & 1;
    int pos = (p < 4) ? (p << 1) : (((p - 4) << 1) + 1);
    return (k & ~15) + (pos << 1) + bb;
}
__device__ __forceinline__ uint32_t mapa_u32(uint32_t addr, uint32_t rank) {
    uint32_t r; asm("mapa.shared::cluster.u32 %0, %1, %2;" : "=r"(r) : "r"(addr), "r"(rank)); return r;
}
__device__ __forceinline__ void cluster_sync() {
    asm volatile("barrier.cluster.arrive.aligned;" ::: "memory");
    asm volatile("barrier.cluster.wait.aligned;" ::: "memory");
}
__device__ __forceinline__ uint2 lds2(uint32_t a) {
    uint2 v; asm volatile("ld.shared.v2.u32 {%0,%1}, [%2];" : "=r"(v.x), "=r"(v.y) : "r"(a)); return v;
}
__device__ __forceinline__ uint2 ldsc2(uint32_t a) {
    uint2 v; asm volatile("ld.shared::cluster.v2.u32 {%0,%1}, [%2];" : "=r"(v.x), "=r"(v.y) : "r"(a)); return v;
}
__device__ __forceinline__ float ldscf(uint32_t a) {
    float v; asm volatile("ld.shared::cluster.f32 %0, [%1];" : "=f"(v) : "r"(a)); return v;
}

// ---------------- prep: weights -> per-lane fragment-order step images (same as R9) ----------------
__global__ void prep_kernel(const float* __restrict__ conv_w, const float* __restrict__ proj_w) {
    const int gs = blockIdx.x, t = threadIdx.x;
    const int lane = t & 31, sp = (t >> 5) & 1, mgq = t >> 6;
    const int gr = lane >> 2, lc = lane & 3;
    int base, l = 0, tap = 0;
    bool proj;
    if (gs < 64) { proj = true; base = gs * 16; }
    else { int tt = gs - 64; l = tt >> 5; int c = tt & 31; tap = c >> 4; base = (c & 15) * 16; proj = false; }
    for (int mgi = 0; mgi < 4; mgi++) {
        int mg = mgq * 4 + mgi;
        int m0 = mg * 16 + gr, m1 = m0 + 8;
        int c0 = base + lc * 2, c2 = c0 + 8;
        float w[8];
        if (proj) {
            w[0] = proj_w[(size_t)m0 * 1024 + c0]; w[1] = proj_w[(size_t)m0 * 1024 + c0 + 1];
            w[2] = proj_w[(size_t)m1 * 1024 + c0]; w[3] = proj_w[(size_t)m1 * 1024 + c0 + 1];
            w[4] = proj_w[(size_t)m0 * 1024 + c2]; w[5] = proj_w[(size_t)m0 * 1024 + c2 + 1];
            w[6] = proj_w[(size_t)m1 * 1024 + c2]; w[7] = proj_w[(size_t)m1 * 1024 + c2 + 1];
        } else {
            const float* cw = conv_w + (size_t)l * 256 * 256 * 2 + tap;
            w[0] = cw[((size_t)m0 * 256 + c0) * 2]; w[1] = cw[((size_t)m0 * 256 + c0 + 1) * 2];
            w[2] = cw[((size_t)m1 * 256 + c0) * 2]; w[3] = cw[((size_t)m1 * 256 + c0 + 1) * 2];
            w[4] = cw[((size_t)m0 * 256 + c2) * 2]; w[5] = cw[((size_t)m0 * 256 + c2 + 1) * 2];
            w[6] = cw[((size_t)m1 * 256 + c2) * 2]; w[7] = cw[((size_t)m1 * 256 + c2 + 1) * 2];
        }
        uint32_t u[4];
        #pragma unroll
        for (int i = 0; i < 4; i++)
            u[i] = (uint32_t)spc(w[i * 2], sp) | ((uint32_t)spc(w[i * 2 + 1], sp) << 16);
        *(uint4*)(gW + ((size_t)(gs * 16 + mg) * 2 + sp) * 512 + lane * 16) =
            make_uint4(u[0], u[1], u[2], u[3]);
    }
}

// ---------------- pipeline helpers ----------------
__device__ __forceinline__ void wait1() { asm volatile("cp.async.wait_group 1;" ::: "memory"); }
__device__ __forceinline__ void wait0() { asm volatile("cp.async.wait_group 0;" ::: "memory"); }

// warp = 32m slice: copies its OWN 2KB (2 mg x 2 splits), zero sync
__device__ __forceinline__ void issue_step(uint32_t sbase, int s2, int warp, int lane) {
    uint32_t dst = sbase + ((s2 & 1) ? A1_OFF : A0_OFF) + (warp << 11) + (lane << 4);
    const unsigned char* src = gW + ((size_t)s2 * 16 + warp * 2) * 1024 + lane * 16;
    #pragma unroll
    for (int q = 0; q < 4; q++)
        asm volatile("cp.async.cg.shared.global [%0], [%1], 16;"
                     :: "r"(dst + q * 512), "l"(src + q * 512));
    asm volatile("cp.async.commit_group;");
}

// one 16-k step: warp tile 32m x 64t. A from SMEM (local), B via address table (local or cluster).
template<bool CL>
__device__ __forceinline__ void gemm16t(
    float (&d)[2][8][4], const unsigned char* A, const uint32_t* aB, int cb, int nv)
{
    uint4 ah[2], al[2];
    ah[0] = *(const uint4*)(A);        al[0] = *(const uint4*)(A + 512);
    ah[1] = *(const uint4*)(A + 1024); al[1] = *(const uint4*)(A + 1536);
    #pragma unroll
    for (int ih = 0; ih < 2; ih++) {
        uint2 bh[4], bl[4];
        #pragma unroll
        for (int nj = 0; nj < 4; nj++) {
            int ni = ih * 4 + nj;
            if (ni < nv) {
                uint32_t ad = aB[ni] + cb;
                if (CL) { bh[nj] = ldsc2(ad); bl[nj] = ldsc2(ad + BSPLH); }
                else    { bh[nj] = lds2(ad);  bl[nj] = lds2(ad + BSPLH); }
            }
        }
        #pragma unroll
        for (int nj = 0; nj < 4; nj++) {            // w_hi * h_hi
            int ni = ih * 4 + nj;
            if (ni < nv)
                #pragma unroll
                for (int mi = 0; mi < 2; mi++)
                    mma_bf16(d[mi][ni], ah[mi].x, ah[mi].y, ah[mi].z, ah[mi].w, bh[nj].x, bh[nj].y);
        }
        #pragma unroll
        for (int nj = 0; nj < 4; nj++) {            // w_lo * h_hi
            int ni = ih * 4 + nj;
            if (ni < nv)
                #pragma unroll
                for (int mi = 0; mi < 2; mi++)
                    mma_bf16(d[mi][ni], al[mi].x, al[mi].y, al[mi].z, al[mi].w, bh[nj].x, bh[nj].y);
        }
        #pragma unroll
        for (int nj = 0; nj < 4; nj++) {            // w_hi * h_lo
            int ni = ih * 4 + nj;
            if (ni < nv)
                #pragma unroll
                for (int mi = 0; mi < 2; mi++)
                    mma_bf16(d[mi][ni], ah[mi].x, ah[mi].y, ah[mi].z, ah[mi].w, bl[nj].x, bl[nj].y);
        }
    }
}

// ---------------- main: cluster of 2 CTAs per batch, each owns 64 t ----------------
__global__ __launch_bounds__(256, 2) __cluster_dims__(2, 1, 1)
void Model_26147760898465_kernel(
    const float* __restrict__ x,
    const float* __restrict__ proj_b, const float* __restrict__ conv_b,
    const float* __restrict__ ev_w,  const float* __restrict__ ev_b,
    const float* __restrict__ sw_w,  const float* __restrict__ sw_b,
    float* __restrict__ out)
{
    extern __shared__ unsigned char sm[];
    __nv_bfloat16* Bhi = (__nv_bfloat16*)sm;
    __nv_bfloat16* Blo = (__nv_bfloat16*)(sm + BSPLH);

    const int tid = threadIdx.x, warp = tid >> 5, lane = tid & 31;
    const int gr = lane >> 2, lc = lane & 3;
    const int r = blockIdx.x & 1;               // cluster rank (t-half)
    const int b = blockIdx.x >> 1;              // batch
    const int mo = warp * 32;                   // warp m-slice
    const uint32_t sbase = (uint32_t)__cvta_generic_to_shared(sm);
    const int pmb = 2 * (gr & ~1) + (gr & 1);

    // tap-1 (unshifted) B row addresses: always local
    uint32_t a1[8];
    #pragma unroll
    for (int ni = 0; ni < 8; ni++)
        a1[ni] = sbase + (uint32_t)(ni * 8 + gr) * SBB + lc * 8;

    // prologue: prefetch steps 0,1
    issue_step(sbase, 0, warp, lane);
    issue_step(sbase, 1, warp, lane);

    // zero pad rows 64..67 of both splits (OOB tap-2 target; stays zero)
    for (int i = tid; i < 4 * SBW; i += 256) {
        Bhi[64 * SBW + i] = __float2bfloat16(0.f);
        Blo[64 * SBW + i] = __float2bfloat16(0.f);
    }

    float d[2][8][4];
    #pragma unroll
    for (int mi = 0; mi < 2; mi++)
        #pragma unroll
        for (int ni = 0; ni < 8; ni++)
            #pragma unroll
            for (int q = 0; q < 4; q++) d[mi][ni][q] = 0.f;

    // ======== projection: 4 passes x 16 steps (all local B) ========
    for (int p = 0; p < 4; p++) {
        __syncthreads();
        {   // build B (64 local t x 256 chans, permuted pairs) from x
            int cp = tid & 127, th = tid >> 7;
            int p7 = cp & 7;
            int widx = (cp & ~7) + (p7 < 4 ? 2 * p7 : 2 * (p7 - 4) + 1);
            const float* xp0 = x + ((size_t)b * 1024 + p * 256 + cp * 2) * TLEN + r * 64;
            const float* xp1 = xp0 + TLEN;
            for (int q = 0; q < 8; q++) {
                int t = th * 32 + q * 4;
                float4 v0 = *(const float4*)(xp0 + t);
                float4 v1 = *(const float4*)(xp1 + t);
                float e0[4] = {v0.x, v0.y, v0.z, v0.w};
                float e1[4] = {v1.x, v1.y, v1.z, v1.w};
                #pragma unroll
                for (int j = 0; j < 4; j++) {
                    __nv_bfloat16 h0, l0, h1, l1;
                    split2(e0[j], h0, l0); split2(e1[j], h1, l1);
                    ((uint32_t*)Bhi)[(t + j) * (SBW / 2) + widx] =
                        (uint32_t)__bfloat16_as_ushort(h0) | ((uint32_t)__bfloat16_as_ushort(h1) << 16);
                    ((uint32_t*)Blo)[(t + j) * (SBW / 2) + widx] =
                        (uint32_t)__bfloat16_as_ushort(l0) | ((uint32_t)__bfloat16_as_ushort(l1) << 16);
                }
            }
        }
        __syncthreads();
        for (int q = 0; q < 16; q++) {
            int s = p * 16 + q;
            wait1();
            const unsigned char* A = sm + ((s & 1) ? A1_OFF : A0_OFF) + (warp << 11) + (lane << 4);
            gemm16t<false>(d, A, a1, q * 32, 8);
            issue_step(sbase, s + 2, warp, lane);
        }
    }
    __syncthreads();
    // proj epilogue: bias, write splits
    {
        float bias[2][2];
        #pragma unroll
        for (int mi = 0; mi < 2; mi++) {
            bias[mi][0] = __ldg(proj_b + mo + mi * 16 + gr);
            bias[mi][1] = __ldg(proj_b + mo + mi * 16 + gr + 8);
        }
        #pragma unroll
        for (int mi = 0; mi < 2; mi++)
            #pragma unroll
            for (int ni = 0; ni < 8; ni++)
                #pragma unroll
                for (int q = 0; q < 4; q++) {
                    int rb = q >> 1;
                    int ms = mo + mi * 16 + pmb + 2 * rb;
                    int t = ni * 8 + lc * 2 + (q & 1);
                    float y = d[mi][ni][q] + bias[mi][rb];
                    __nv_bfloat16 hi, lo; split2(y, hi, lo);
                    Bhi[t * SBW + ms] = hi; Blo[t * SBW + ms] = lo;
                }
    }
    cluster_sync();   // h visible cluster-wide before layer 0 tap-2 reads

    // ======== 8 conv layers ========
    const int DILS[8] = {1, 2, 4, 8, 16, 32, 64, 1};
    for (int l = 0; l < 8; l++) {
        const int D = DILS[l];
        // per-layer tap-2 address table (local / peer via mapa / zero row)
        uint32_t a2[8];
        #pragma unroll
        for (int ni = 0; ni < 8; ni++) {
            int tg = 64 * r + ni * 8 + gr + D;
            uint32_t ad;
            if (tg > 127) ad = mapa_u32(sbase + (uint32_t)(64 + (gr & 3)) * SBB + lc * 8, (uint32_t)r);
            else {
                int own = tg >> 6;
                ad = mapa_u32(sbase + (uint32_t)(tg & 63) * SBB + lc * 8, (uint32_t)own);
            }
            a2[ni] = ad;
        }
        int nv2 = (127 - D - 64 * r) >> 3;       // last fully-engaged ni (lane gr=0)
        nv2 = nv2 < 0 ? 0 : (nv2 >= 7 ? 8 : nv2 + 1);

        #pragma unroll
        for (int mi = 0; mi < 2; mi++)
            #pragma unroll
            for (int ni = 0; ni < 8; ni++)
                #pragma unroll
                for (int q = 0; q < 4; q++) d[mi][ni][q] = 0.f;

        const int s0 = 64 + l * 32;
        for (int c = 0; c < 16; c++) {           // tap 0 (local)
            int s = s0 + c;
            wait1();
            const unsigned char* A = sm + ((s & 1) ? A1_OFF : A0_OFF) + (warp << 11) + (lane << 4);
            gemm16t<false>(d, A, a1, c * 32, 8);
            issue_step(sbase, s + 2, warp, lane);
        }
        for (int c = 0; c < 16; c++) {           // tap 1 (shifted: local/peer/zero)
            int s = s0 + 16 + c;
            if (s == NSTEP - 1) wait0(); else wait1();
            const unsigned char* A = sm + ((s & 1) ? A1_OFF : A0_OFF) + (warp << 11) + (lane << 4);
            gemm16t<true>(d, A, a2, c * 32, nv2);
            if (s + 2 < NSTEP) issue_step(sbase, s + 2, warp, lane);
        }
        cluster_sync();   // all cluster reads of current h done before overwrite

        // epilogue: bias + leaky + skip + unit-norm (per-t over full 256 chans, local)
        float* scr = (float*)(sm + SCR_OFF);
        float* colfac = (float*)(sm + CF_OFF);
        float bias[2][2];
        #pragma unroll
        for (int mi = 0; mi < 2; mi++) {
            bias[mi][0] = __ldg(conv_b + l * HID + mo + mi * 16 + gr);
            bias[mi][1] = __ldg(conv_b + l * HID + mo + mi * 16 + gr + 8);
        }
        float ps[8][2];
        #pragma unroll
        for (int ni = 0; ni < 8; ni++) { ps[ni][0] = 0.f; ps[ni][1] = 0.f; }
        #pragma unroll
        for (int mi = 0; mi < 2; mi++)
            #pragma unroll
            for (int ni = 0; ni < 8; ni++)
                #pragma unroll
                for (int q = 0; q < 4; q++) {
                    int rb = q >> 1;
                    int ms = mo + mi * 16 + pmb + 2 * rb;
                    int t = ni * 8 + lc * 2 + (q & 1);
                    float y = d[mi][ni][q] + bias[mi][rb];
                    y = (y > 0.f) ? y : 0.2f * y;
                    y += __bfloat162float(Bhi[t * SBW + ms]) + __bfloat162float(Blo[t * SBW + ms]);
                    d[mi][ni][q] = y;
                    ps[ni][q & 1] = fmaf(y, y, ps[ni][q & 1]);
                }
        #pragma unroll
        for (int ni = 0; ni < 8; ni++)
            #pragma unroll
            for (int j = 0; j < 2; j++) {
                float v = ps[ni][j];
                v += __shfl_down_sync(0xffffffffu, v, 16);
                v += __shfl_down_sync(0xffffffffu, v, 8);
                v += __shfl_down_sync(0xffffffffu, v, 4);
                ps[ni][j] = v;
            }
        if (lane < 4) {
            #pragma unroll
            for (int ni = 0; ni < 8; ni++)
                #pragma unroll
                for (int j = 0; j < 2; j++)
                    scr[warp * 64 + ni * 8 + lane * 2 + j] = ps[ni][j];
        }
        __syncthreads();
        if (tid < 64) {
            float s = 0.f;
            #pragma unroll
            for (int g = 0; g < 8; g++) s += scr[g * 64 + tid];
            colfac[tid] = 1.0f / (sqrtf(s) + 1e-8f);
        }
        __syncthreads();
        float cf[8][2];
        #pragma unroll
        for (int ni = 0; ni < 8; ni++) {
            cf[ni][0] = colfac[ni * 8 + lc * 2];
            cf[ni][1] = colfac[ni * 8 + lc * 2 + 1];
        }
        #pragma unroll
        for (int mi = 0; mi < 2; mi++)
            #pragma unroll
            for (int ni = 0; ni < 8; ni++)
                #pragma unroll
                for (int q = 0; q < 4; q++) {
                    int rb = q >> 1;
                    int ms = mo + mi * 16 + pmb + 2 * rb;
                    int t = ni * 8 + lc * 2 + (q & 1);
                    float y = d[mi][ni][q] * cf[ni][q & 1];
                    __nv_bfloat16 hi, lo; split2(y, hi, lo);
                    Bhi[t * SBW + ms] = hi; Blo[t * SBW + ms] = lo;
                }
        cluster_sync();   // new h visible cluster-wide
    }

    // ======== heads (A pipeline drained at step 319) ========
    float* evw  = (float*)(sm + EVW_OFF);
    float* sww  = (float*)(sm + SWW_OFF);
    float* evs  = (float*)(sm + EVS_OFF);       // [16][64]
    float* attn = (float*)(sm + ATT_OFF);       // [64]
    float* att2 = (float*)(sm + SCR_OFF);       // peer attn (rank0 only)
    float* redv = (float*)(sm + RED_OFF);
    int*   redi = (int*)(sm + RED_OFF + 16);
    for (int i = tid; i < CTXD * HID; i += 256) {
        int cc = i >> 8, k = i & 255;
        evw[cc * HID + PERMC(k)] = __ldg(ev_w + i);
    }
    sww[PERMC(tid)] = __ldg(sw_w + tid);
    __syncthreads();
    if (tid < 64) {
        float a[CTXD + 1];
        #pragma unroll
        for (int cc = 0; cc < CTXD; cc++) a[cc] = __ldg(ev_b + cc);
        a[CTXD] = __ldg(sw_b);
        for (int i = 0; i < HID; i++) {
            float hv = __bfloat162float(Bhi[tid * SBW + i]) + __bfloat162float(Blo[tid * SBW + i]);
            #pragma unroll
            for (int cc = 0; cc < CTXD; cc++) a[cc] = fmaf(evw[cc * HID + i], hv, a[cc]);
            a[CTXD] = fmaf(sww[i], hv, a[CTXD]);
        }
        #pragma unroll
        for (int cc = 0; cc < CTXD; cc++) evs[cc * 64 + tid] = a[cc];
        attn[tid] = fmaxf(a[CTXD], 0.f);
    }
    cluster_sync();   // both halves' attn/evs ready

    if (r == 0) {
        const int Btot = (int)(gridDim.x >> 1);
        uint32_t peer_att = mapa_u32(sbase + ATT_OFF, 1u);
        uint32_t peer_evs = mapa_u32(sbase + EVS_OFF, 1u);
        if (tid < 64) att2[tid] = ldscf(peer_att + tid * 4);
        __syncthreads();
        if (tid < TLEN) {
            float v = (tid < 64) ? attn[tid] : att2[tid - 64];
            int idx = tid;
            #pragma unroll
            for (int off = 16; off > 0; off >>= 1) {
                float ov = __shfl_down_sync(0xffffffffu, v, off);
                int   oi = __shfl_down_sync(0xffffffffu, idx, off);
                if (ov > v || (ov == v && oi < idx)) { v = ov; idx = oi; }
            }
            if (lane == 0) { redv[warp] = v; redi[warp] = idx; }
        }
        __syncthreads();
        if (tid == 0) {
            float v = redv[0]; int idx = redi[0];
            for (int w = 1; w < 4; w++)
                if (redv[w] > v || (redv[w] == v && redi[w] < idx)) { v = redv[w]; idx = redi[w]; }
            redv[0] = v; redi[0] = idx;
        }
        __syncthreads();
        const int bi = redi[0]; const float bv = redv[0];
        if (tid < CTXD) {
            float val = (bi < 64) ? evs[tid * 64 + bi]
                                  : ldscf(peer_evs + (tid * 64 + (bi - 64)) * 4);
            out[(size_t)b * CTXD + tid] = val;
        }
        if (tid < TLEN)
            out[(size_t)Btot * CTXD + (size_t)b * TLEN + tid] = (tid == bi) ? bv : 0.f;
    }
    cluster_sync();   // keep peer smem alive until rank0's reads complete
}

extern "C" void kernel_launch(void* const* d_in, const int* in_sizes, int n_in,
                              void* d_out, int out_size)
{
    const float* x      = (const float*)d_in[0];
    const float* proj_w = (const float*)d_in[1];
    const float* proj_b = (const float*)d_in[2];
    const float* conv_w = (const float*)d_in[3];
    const float* conv_b = (const float*)d_in[4];
    const float* ev_w   = (const float*)d_in[5];
    const float* ev_b   = (const float*)d_in[6];
    const float* sw_w   = (const float*)d_in[7];
    const float* sw_b   = (const float*)d_in[8];
    float* out = (float*)d_out;
    const int B = in_sizes[0] / (1024 * TLEN);   // 256

    prep_kernel<<<NSTEP, 256>>>(conv_w, proj_w);
    cudaFuncSetAttribute(Model_26147760898465_kernel,
                         cudaFuncAttributeMaxDynamicSharedMemorySize, SMEM_BYTES);
    Model_26147760898465_kernel<<<2 * B, 256, SMEM_BYTES>>>(
        x, proj_b, conv_b, ev_w, ev_b, sw_w, sw_b, out);
}

// round 14
// speedup vs baseline: 1.1098x; 1.1098x over previous
#include <cuda_runtime.h>
#include <cuda_bf16.h>
#include <cstdint>

#define TLEN 128
#define HID  256
#define CTXD 16

#define SBW 280                 // B row stride (bf16 units)
#define SBB 560                 // B row stride (bytes)
#define BSPL 73920              // one B split: 132 rows * 560B
#define A0_OFF 147840           // A buffer 0 (32 KB)
#define A1_OFF 180608           // A buffer 1 (32 KB)
#define SCR_OFF 213376
#define CF_OFF  215424
#define RV_OFF  215936
#define RI_OFF  215952
#define SMEM_BYTES 215968
// head overlay (A region; pipeline drained by then)
#define PA_OFF  147840          // [2][17][128] f32 = 17408 B
#define EVW_OFF 165248          // 16x256 f32
#define SWW_OFF 181632          // 256 f32
#define EVS_OFF 182656          // 16x128 f32
#define ATT_OFF 190848          // 128 f32

#define NSTEP 320               // 64 proj + 8*32 conv, 16 k-units each
__device__ __align__(1024) unsigned char gW[(size_t)NSTEP * 16384];

__device__ __forceinline__ void mma_bf16(float* d, uint32_t a0, uint32_t a1, uint32_t a2, uint32_t a3,
                                         uint32_t b0, uint32_t b1) {
    asm("mma.sync.aligned.m16n8k16.row.col.f32.bf16.bf16.f32 "
        "{%0,%1,%2,%3}, {%4,%5,%6,%7}, {%8,%9}, {%0,%1,%2,%3};"
        : "+f"(d[0]), "+f"(d[1]), "+f"(d[2]), "+f"(d[3])
        : "r"(a0), "r"(a1), "r"(a2), "r"(a3), "r"(b0), "r"(b1));
}
__device__ __forceinline__ void split2(float w, __nv_bfloat16& hi, __nv_bfloat16& lo) {
    hi = __float2bfloat16(w);
    lo = __float2bfloat16(w - __bfloat162float(hi));
}
__device__ __forceinline__ unsigned short spc(float w, int sp) {
    __nv_bfloat16 hi = __float2bfloat16(w);
    if (sp == 0) return __bfloat16_as_ushort(hi);
    return __bfloat16_as_ushort(__float2bfloat16(w - __bfloat162float(hi)));
}
__device__ __forceinline__ int PERMC(int k) {
    int v = k & 15, p = v >> 1, bb = v & 1;
    int pos = (p < 4) ? (p << 1) : (((p - 4) << 1) + 1);
    return (k & ~15) + (pos << 1) + bb;
}

// ---------------- prep: weights -> per-lane fragment-order step images (same as R9) ----------------
__global__ void prep_kernel(const float* __restrict__ conv_w, const float* __restrict__ proj_w) {
    const int gs = blockIdx.x, t = threadIdx.x;
    const int lane = t & 31, sp = (t >> 5) & 1, mgq = t >> 6;
    const int gr = lane >> 2, lc = lane & 3;
    int base, l = 0, tap = 0;
    bool proj;
    if (gs < 64) { proj = true; base = gs * 16; }
    else { int tt = gs - 64; l = tt >> 5; int c = tt & 31; tap = c >> 4; base = (c & 15) * 16; proj = false; }
    for (int mgi = 0; mgi < 4; mgi++) {
        int mg = mgq * 4 + mgi;
        int m0 = mg * 16 + gr, m1 = m0 + 8;
        int c0 = base + lc * 2, c2 = c0 + 8;
        float w[8];
        if (proj) {
            w[0] = proj_w[(size_t)m0 * 1024 + c0]; w[1] = proj_w[(size_t)m0 * 1024 + c0 + 1];
            w[2] = proj_w[(size_t)m1 * 1024 + c0]; w[3] = proj_w[(size_t)m1 * 1024 + c0 + 1];
            w[4] = proj_w[(size_t)m0 * 1024 + c2]; w[5] = proj_w[(size_t)m0 * 1024 + c2 + 1];
            w[6] = proj_w[(size_t)m1 * 1024 + c2]; w[7] = proj_w[(size_t)m1 * 1024 + c2 + 1];
        } else {
            const float* cw = conv_w + (size_t)l * 256 * 256 * 2 + tap;
            w[0] = cw[((size_t)m0 * 256 + c0) * 2]; w[1] = cw[((size_t)m0 * 256 + c0 + 1) * 2];
            w[2] = cw[((size_t)m1 * 256 + c0) * 2]; w[3] = cw[((size_t)m1 * 256 + c0 + 1) * 2];
            w[4] = cw[((size_t)m0 * 256 + c2) * 2]; w[5] = cw[((size_t)m0 * 256 + c2 + 1) * 2];
            w[6] = cw[((size_t)m1 * 256 + c2) * 2]; w[7] = cw[((size_t)m1 * 256 + c2 + 1) * 2];
        }
        uint32_t u[4];
        #pragma unroll
        for (int i = 0; i < 4; i++)
            u[i] = (uint32_t)spc(w[i * 2], sp) | ((uint32_t)spc(w[i * 2 + 1], sp) << 16);
        *(uint4*)(gW + ((size_t)(gs * 16 + mg) * 2 + sp) * 512 + lane * 16) =
            make_uint4(u[0], u[1], u[2], u[3]);
    }
}

// ---------------- pipeline helpers ----------------
__device__ __forceinline__ void wait1() { asm volatile("cp.async.wait_group 1;" ::: "memory"); }
__device__ __forceinline__ void wait0() { asm volatile("cp.async.wait_group 0;" ::: "memory"); }

__device__ __forceinline__ void issue_step(uint32_t sbase, int s2, int mgbase, int warp, int lane) {
    uint32_t dst = sbase + ((s2 & 1) ? A1_OFF : A0_OFF) + (warp << 12) + (lane << 4);
    const unsigned char* src = gW + ((size_t)s2 * 16 + mgbase) * 1024 + lane * 16;
    #pragma unroll
    for (int q = 0; q < 8; q++)
        asm volatile("cp.async.cg.shared.global [%0], [%1], 16;"
                     :: "r"(dst + q * 512), "l"(src + q * 512));
    asm volatile("cp.async.commit_group;");
}

// one 16-k step: B(ih0) loads -> wait -> A loads -> issue s+2 -> MMAs (split-major)
__device__ __forceinline__ void step16(
    float (&d)[4][8][4], const unsigned char* sm, uint32_t sbase,
    int s, int warp, int lane, int mgbase,
    const int* brow, int cb, int shiftB, int nv)
{
    const unsigned char* Bh = sm;
    const unsigned char* Bl = sm + BSPL;
    // first-half B fragments BEFORE the wait (independent of A buffer)
    uint2 bh0[4], bl0[4];
    #pragma unroll
    for (int nj = 0; nj < 4; nj++) {
        if (nj < nv) {
            int bb = brow[nj] + shiftB + cb;
            bh0[nj] = *(const uint2*)(Bh + bb);
            bl0[nj] = *(const uint2*)(Bl + bb);
        }
    }
    if (s == NSTEP - 1) wait0(); else wait1();
    const unsigned char* Af = sm + ((s & 1) ? A1_OFF : A0_OFF) + (warp << 12) + (lane << 4);
    uint4 ah[4], al[4];
    #pragma unroll
    for (int mi = 0; mi < 4; mi++) {
        ah[mi] = *(const uint4*)(Af + mi * 1024);
        al[mi] = *(const uint4*)(Af + mi * 1024 + 512);
    }
    // issue next copy early: own slice only; same-warp LSU order keeps prior LDS ahead
    if (s + 2 < NSTEP) issue_step(sbase, s + 2, mgbase, warp, lane);

    #pragma unroll
    for (int nj = 0; nj < 4; nj++)
        if (nj < nv)
            #pragma unroll
            for (int mi = 0; mi < 4; mi++)
                mma_bf16(d[mi][nj], ah[mi].x, ah[mi].y, ah[mi].z, ah[mi].w, bh0[nj].x, bh0[nj].y);
    #pragma unroll
    for (int nj = 0; nj < 4; nj++)
        if (nj < nv)
            #pragma unroll
            for (int mi = 0; mi < 4; mi++)
                mma_bf16(d[mi][nj], al[mi].x, al[mi].y, al[mi].z, al[mi].w, bh0[nj].x, bh0[nj].y);
    #pragma unroll
    for (int nj = 0; nj < 4; nj++)
        if (nj < nv)
            #pragma unroll
            for (int mi = 0; mi < 4; mi++)
                mma_bf16(d[mi][nj], ah[mi].x, ah[mi].y, ah[mi].z, ah[mi].w, bl0[nj].x, bl0[nj].y);

    // second half
    uint2 bh1[4], bl1[4];
    #pragma unroll
    for (int nj = 0; nj < 4; nj++) {
        int ni = 4 + nj;
        if (ni < nv) {
            int bb = brow[ni] + shiftB + cb;
            bh1[nj] = *(const uint2*)(Bh + bb);
            bl1[nj] = *(const uint2*)(Bl + bb);
        }
    }
    #pragma unroll
    for (int nj = 0; nj < 4; nj++)
        if (4 + nj < nv)
            #pragma unroll
            for (int mi = 0; mi < 4; mi++)
                mma_bf16(d[mi][4 + nj], ah[mi].x, ah[mi].y, ah[mi].z, ah[mi].w, bh1[nj].x, bh1[nj].y);
    #pragma unroll
    for (int nj = 0; nj < 4; nj++)
        if (4 + nj < nv)
            #pragma unroll
            for (int mi = 0; mi < 4; mi++)
                mma_bf16(d[mi][4 + nj], al[mi].x, al[mi].y, al[mi].z, al[mi].w, bh1[nj].x, bh1[nj].y);
    #pragma unroll
    for (int nj = 0; nj < 4; nj++)
        if (4 + nj < nv)
            #pragma unroll
            for (int mi = 0; mi < 4; mi++)
                mma_bf16(d[mi][4 + nj], ah[mi].x, ah[mi].y, ah[mi].z, ah[mi].w, bl1[nj].x, bl1[nj].y);
}

// ---------------- main ----------------
__global__ __launch_bounds__(256, 1)
void Model_26147760898465_kernel(
    const float* __restrict__ x,
    const float* __restrict__ proj_b, const float* __restrict__ conv_b,
    const float* __restrict__ ev_w,  const float* __restrict__ ev_b,
    const float* __restrict__ sw_w,  const float* __restrict__ sw_b,
    float* __restrict__ out)
{
    extern __shared__ unsigned char sm[];
    __nv_bfloat16* Bhi = (__nv_bfloat16*)sm;
    __nv_bfloat16* Blo = (__nv_bfloat16*)(sm + BSPL);

    const int tid = threadIdx.x, warp = tid >> 5, lane = tid & 31;
    const int gr = lane >> 2, lc = lane & 3, b = blockIdx.x;
    const int mo = (warp & 3) * 64, to = (warp >> 2) * 64;
    const int mgbase = (warp & 3) * 4;
    const uint32_t sbase = (uint32_t)__cvta_generic_to_shared(sm);
    const int pmb = 2 * (gr & ~1) + (gr & 1);

    int brow[8];
    #pragma unroll
    for (int ni = 0; ni < 8; ni++) brow[ni] = (to + ni * 8 + gr) * SBB + lc * 8;

    // prologue: prefetch steps 0,1
    issue_step(sbase, 0, mgbase, warp, lane);
    issue_step(sbase, 1, mgbase, warp, lane);

    // zero pad rows 128..131 of both B splits
    for (int i = tid; i < 4 * SBW; i += 256) {
        Bhi[128 * SBW + i] = __float2bfloat16(0.f);
        Blo[128 * SBW + i] = __float2bfloat16(0.f);
    }

    float d[4][8][4];
    #pragma unroll
    for (int mi = 0; mi < 4; mi++)
        #pragma unroll
        for (int ni = 0; ni < 8; ni++)
            #pragma unroll
            for (int r = 0; r < 4; r++) d[mi][ni][r] = 0.f;

    // ======== projection: 4 passes x 16 steps ========
    for (int p = 0; p < 4; p++) {
        __syncthreads();   // prev pass gemm reads done
        {   // build B (permuted pair positions) from x
            int cp = tid & 127, th = tid >> 7;
            int p7 = cp & 7;
            int widx = (cp & ~7) + (p7 < 4 ? 2 * p7 : 2 * (p7 - 4) + 1);
            const float* xp0 = x + ((size_t)b * 1024 + p * 256 + cp * 2) * TLEN;
            const float* xp1 = xp0 + TLEN;
            for (int q = 0; q < 16; q++) {
                int t = th * 64 + q * 4;
                float4 v0 = *(const float4*)(xp0 + t);
                float4 v1 = *(const float4*)(xp1 + t);
                float a0[4] = {v0.x, v0.y, v0.z, v0.w};
                float a1[4] = {v1.x, v1.y, v1.z, v1.w};
                #pragma unroll
                for (int j = 0; j < 4; j++) {
                    __nv_bfloat16 h0, l0, h1, l1;
                    split2(a0[j], h0, l0); split2(a1[j], h1, l1);
                    ((uint32_t*)Bhi)[(t + j) * (SBW / 2) + widx] =
                        (uint32_t)__bfloat16_as_ushort(h0) | ((uint32_t)__bfloat16_as_ushort(h1) << 16);
                    ((uint32_t*)Blo)[(t + j) * (SBW / 2) + widx] =
                        (uint32_t)__bfloat16_as_ushort(l0) | ((uint32_t)__bfloat16_as_ushort(l1) << 16);
                }
            }
        }
        __syncthreads();
        for (int q = 0; q < 16; q++)
            step16(d, sm, sbase, p * 16 + q, warp, lane, mgbase, brow, q * 32, 0, 8);
    }
    __syncthreads();   // all warps done reading B before overwrite
    // proj epilogue: bias, write splits (permuted chans)
    {
        float bias[4][2];
        #pragma unroll
        for (int mi = 0; mi < 4; mi++) {
            bias[mi][0] = __ldg(proj_b + mo + mi * 16 + gr);
            bias[mi][1] = __ldg(proj_b + mo + mi * 16 + gr + 8);
        }
        #pragma unroll
        for (int mi = 0; mi < 4; mi++)
            #pragma unroll
            for (int ni = 0; ni < 8; ni++)
                #pragma unroll
                for (int r = 0; r < 4; r++) {
                    int rb = r >> 1;
                    int ms = mo + mi * 16 + pmb + 2 * rb;
                    int t = to + ni * 8 + lc * 2 + (r & 1);
                    float y = d[mi][ni][r] + bias[mi][rb];
                    __nv_bfloat16 hi, lo; split2(y, hi, lo);
                    Bhi[t * SBW + ms] = hi; Blo[t * SBW + ms] = lo;
                }
        __syncthreads();
    }

    // ======== 8 conv layers: 32 steps each ========
    const int DILS[8] = {1, 2, 4, 8, 16, 32, 64, 1};
    for (int l = 0; l < 8; l++) {
        const int D = DILS[l];
        #pragma unroll
        for (int mi = 0; mi < 4; mi++)
            #pragma unroll
            for (int ni = 0; ni < 8; ni++)
                #pragma unroll
                for (int r = 0; r < 4; r++) d[mi][ni][r] = 0.f;

        const int s0 = 64 + l * 32;
        int nvD = 8;
        if (D >= 8) { int nn = (128 - D - to) >> 3; nvD = nn < 0 ? 0 : (nn > 8 ? 8 : nn); }

        for (int c = 0; c < 16; c++)          // tap 0: always full
            step16(d, sm, sbase, s0 + c, warp, lane, mgbase, brow, c * 32, 0, 8);
        if (nvD == 8) {
            for (int c = 0; c < 16; c++)      // tap 1, full-engagement fast path
                step16(d, sm, sbase, s0 + 16 + c, warp, lane, mgbase, brow, c * 32, D * SBB, 8);
        } else {
            for (int c = 0; c < 16; c++)      // tap 1, boundary warps
                step16(d, sm, sbase, s0 + 16 + c, warp, lane, mgbase, brow, c * 32, D * SBB, nvD);
        }

        // epilogue: bias + leaky + skip + unit-norm
        float* scr = (float*)(sm + SCR_OFF);
        float* colfac = (float*)(sm + CF_OFF);
        float bias[4][2];
        #pragma unroll
        for (int mi = 0; mi < 4; mi++) {
            bias[mi][0] = __ldg(conv_b + l * HID + mo + mi * 16 + gr);
            bias[mi][1] = __ldg(conv_b + l * HID + mo + mi * 16 + gr + 8);
        }
        float ps[8][2];
        #pragma unroll
        for (int ni = 0; ni < 8; ni++) { ps[ni][0] = 0.f; ps[ni][1] = 0.f; }
        #pragma unroll
        for (int mi = 0; mi < 4; mi++)
            #pragma unroll
            for (int ni = 0; ni < 8; ni++)
                #pragma unroll
                for (int r = 0; r < 4; r++) {
                    int rb = r >> 1;
                    int ms = mo + mi * 16 + pmb + 2 * rb;
                    int t = to + ni * 8 + lc * 2 + (r & 1);
                    float y = d[mi][ni][r] + bias[mi][rb];
                    y = (y > 0.f) ? y : 0.2f * y;
                    y += __bfloat162float(Bhi[t * SBW + ms]) + __bfloat162float(Blo[t * SBW + ms]);
                    d[mi][ni][r] = y;
                    ps[ni][r & 1] = fmaf(y, y, ps[ni][r & 1]);
                }
        #pragma unroll
        for (int ni = 0; ni < 8; ni++)
            #pragma unroll
            for (int j = 0; j < 2; j++) {
                float v = ps[ni][j];
                v += __shfl_down_sync(0xffffffffu, v, 16);
                v += __shfl_down_sync(0xffffffffu, v, 8);
                v += __shfl_down_sync(0xffffffffu, v, 4);
                ps[ni][j] = v;
            }
        if (lane < 4) {
            #pragma unroll
            for (int ni = 0; ni < 8; ni++)
                #pragma unroll
                for (int j = 0; j < 2; j++)
                    scr[(warp & 3) * 128 + to + ni * 8 + lane * 2 + j] = ps[ni][j];
        }
        __syncthreads();
        if (tid < TLEN) {
            float s = scr[tid] + scr[128 + tid] + scr[256 + tid] + scr[384 + tid];
            colfac[tid] = 1.0f / (sqrtf(s) + 1e-8f);
        }
        __syncthreads();
        float cf[8][2];
        #pragma unroll
        for (int ni = 0; ni < 8; ni++) {
            cf[ni][0] = colfac[to + ni * 8 + lc * 2];
            cf[ni][1] = colfac[to + ni * 8 + lc * 2 + 1];
        }
        #pragma unroll
        for (int mi = 0; mi < 4; mi++)
            #pragma unroll
            for (int ni = 0; ni < 8; ni++)
                #pragma unroll
                for (int r = 0; r < 4; r++) {
                    int rb = r >> 1;
                    int ms = mo + mi * 16 + pmb + 2 * rb;
                    int t = to + ni * 8 + lc * 2 + (r & 1);
                    float y = d[mi][ni][r] * cf[ni][r & 1];
                    __nv_bfloat16 hi, lo; split2(y, hi, lo);
                    Bhi[t * SBW + ms] = hi; Blo[t * SBW + ms] = lo;
                }
        __syncthreads();
    }

    // ======== heads: split GEMV over 256 threads, then top-1 ========
    float* pa   = (float*)(sm + PA_OFF);        // [2][17][128]
    float* evw  = (float*)(sm + EVW_OFF);
    float* sww  = (float*)(sm + SWW_OFF);
    float* evs  = (float*)(sm + EVS_OFF);
    float* attn = (float*)(sm + ATT_OFF);
    float* redv = (float*)(sm + RV_OFF);
    int*   redi = (int*)(sm + RI_OFF);
    for (int i = tid; i < CTXD * HID; i += 256) {
        int cc = i >> 8, k = i & 255;
        evw[cc * HID + PERMC(k)] = __ldg(ev_w + i);
    }
    sww[PERMC(tid)] = __ldg(sw_w + tid);
    __syncthreads();
    {
        int t = tid >> 1, hf = tid & 1;
        float a[CTXD + 1];
        #pragma unroll
        for (int cc = 0; cc <= CTXD; cc++) a[cc] = 0.f;
        int i0 = hf * 128;
        for (int i = i0; i < i0 + 128; i++) {
            float hv = __bfloat162float(Bhi[t * SBW + i]) + __bfloat162float(Blo[t * SBW + i]);
            #pragma unroll
            for (int cc = 0; cc < CTXD; cc++) a[cc] = fmaf(evw[cc * HID + i], hv, a[cc]);
            a[CTXD] = fmaf(sww[i], hv, a[CTXD]);
        }
        #pragma unroll
        for (int cc = 0; cc <= CTXD; cc++) pa[(hf * 17 + cc) * 128 + t] = a[cc];
    }
    __syncthreads();
    if (tid < TLEN) {
        #pragma unroll
        for (int cc = 0; cc < CTXD; cc++)
            evs[cc * TLEN + tid] = pa[cc * 128 + tid] + pa[(17 + cc) * 128 + tid] + __ldg(ev_b + cc);
        float sw = pa[16 * 128 + tid] + pa[33 * 128 + tid] + __ldg(sw_b);
        attn[tid] = fmaxf(sw, 0.f);
    }
    __syncthreads();
    if (tid < TLEN) {
        float v = attn[tid]; int idx = tid;
        #pragma unroll
        for (int off = 16; off > 0; off >>= 1) {
            float ov = __shfl_down_sync(0xffffffffu, v, off);
            int   oi = __shfl_down_sync(0xffffffffu, idx, off);
            if (ov > v || (ov == v && oi < idx)) { v = ov; idx = oi; }
        }
        if (lane == 0) { redv[warp] = v; redi[warp] = idx; }
    }
    __syncthreads();
    if (tid == 0) {
        float v = redv[0]; int idx = redi[0];
        for (int w = 1; w < 4; w++)
            if (redv[w] > v || (redv[w] == v && redi[w] < idx)) { v = redv[w]; idx = redi[w]; }
        redv[0] = v; redi[0] = idx;
    }
    __syncthreads();
    const int bi = redi[0]; const float bv = redv[0];
    if (tid < CTXD) out[(size_t)b * CTXD + tid] = evs[tid * TLEN + bi];
    if (tid < TLEN) out[(size_t)gridDim.x * CTXD + (size_t)b * TLEN + tid] = (tid == bi) ? bv : 0.f;
}

extern "C" void kernel_launch(void* const* d_in, const int* in_sizes, int n_in,
                              void* d_out, int out_size)
{
    const float* x      = (const float*)d_in[0];
    const float* proj_w = (const float*)d_in[1];
    const float* proj_b = (const float*)d_in[2];
    const float* conv_w = (const float*)d_in[3];
    const float* conv_b = (const float*)d_in[4];
    const float* ev_w   = (const float*)d_in[5];
    const float* ev_b   = (const float*)d_in[6];
    const float* sw_w   = (const float*)d_in[7];
    const float* sw_b   = (const float*)d_in[8];
    float* out = (float*)d_out;
    const int B = in_sizes[0] / (1024 * TLEN);   // 256

    prep_kernel<<<NSTEP, 256>>>(conv_w, proj_w);
    cudaFuncSetAttribute(Model_26147760898465_kernel,
                         cudaFuncAttributeMaxDynamicSharedMemorySize, SMEM_BYTES);
    Model_26147760898465_kernel<<<B, 256, SMEM_BYTES>>>(
        x, proj_b, conv_b, ev_w, ev_b, sw_w, sw_b, out);
}